// round 2
// baseline (speedup 1.0000x reference)
#include <cuda_runtime.h>
#include <math.h>

// ---------------- scratch (static device globals; no allocation) ----------------
#define BMAX 4096
__device__ __align__(16) float d_h1[BMAX * 8 * 16 * 16];   // after conv1+pool
__device__ __align__(16) float d_h2[BMAX * 16 * 8 * 8];    // after conv2+pool
__device__ __align__(16) float d_feats[BMAX * 32];
__device__ __align__(16) float d_g[BMAX * 16];
__device__ __align__(16) float d_q[BMAX * 16];
__device__ __align__(16) float d_k[BMAX * 16];
__device__ __align__(16) float d_attn[BMAX * 16];
__device__ __align__(16) float d_outpre[BMAX * 2];
__device__ float d_ab[4];                    // bn scale/shift

// ---------------- packed f32x2 helpers (sm_103a FFMA2) ----------------
typedef unsigned long long u64;
__device__ __forceinline__ u64 pk(float lo, float hi) {
    u64 r; asm("mov.b64 %0, {%1,%2};" : "=l"(r) : "f"(lo), "f"(hi)); return r;
}
__device__ __forceinline__ u64 pk1(float v) { return pk(v, v); }
__device__ __forceinline__ u64 fma2(u64 a, u64 b, u64 c) {
    u64 d; asm("fma.rn.f32x2 %0, %1, %2, %3;" : "=l"(d) : "l"(a), "l"(b), "l"(c)); return d;
}
__device__ __forceinline__ u64 mul2(u64 a, u64 b) {
    u64 d; asm("mul.rn.f32x2 %0, %1, %2;" : "=l"(d) : "l"(a), "l"(b)); return d;
}
__device__ __forceinline__ u64 add2(u64 a, u64 b) {
    u64 d; asm("add.rn.f32x2 %0, %1, %2;" : "=l"(d) : "l"(a), "l"(b)); return d;
}
__device__ __forceinline__ float2 up2(u64 v) {
    float2 f; asm("mov.b64 {%0,%1}, %2;" : "=f"(f.x), "=f"(f.y) : "l"(v)); return f;
}

// ---------------- conv1 (1->8, 32x32) + relu + maxpool2 -> 8x16x16 ----------------
__global__ void __launch_bounds__(256) k_conv1(const float* __restrict__ x,
                                               const float* __restrict__ w,
                                               const float* __restrict__ bias) {
    __shared__ float img[1024];
    __shared__ float2 wd[72];
    __shared__ float bs[8];
    int b = blockIdx.x, t = threadIdx.x;
    ((float4*)img)[t & 255] = ((const float4*)x)[b * 256 + (t & 255)];
    if (t < 72) { float v = w[t]; wd[t] = make_float2(v, v); }
    if (t < 8) bs[t] = bias[t];
    __syncthreads();

    int ph = t >> 4, pw = t & 15;
    float p[4][4];
#pragma unroll
    for (int yy = 0; yy < 4; yy++) {
        int iy = 2 * ph - 1 + yy;
#pragma unroll
        for (int xx = 0; xx < 4; xx++) {
            int ix = 2 * pw - 1 + xx;
            p[yy][xx] = ((unsigned)iy < 32u && (unsigned)ix < 32u) ? img[iy * 32 + ix] : 0.f;
        }
    }
    // sliding pairs
    u64 pr[4][3];
#pragma unroll
    for (int yy = 0; yy < 4; yy++)
#pragma unroll
        for (int kx = 0; kx < 3; kx++) pr[yy][kx] = pk(p[yy][kx], p[yy][kx + 1]);

    const u64* wdu = (const u64*)wd;
#pragma unroll
    for (int c = 0; c < 8; c++) {
        u64 aA = pk1(bs[c]), aB = aA;   // (a00,a01) / (a10,a11)
#pragma unroll
        for (int ky = 0; ky < 3; ky++)
#pragma unroll
            for (int kx = 0; kx < 3; kx++) {
                u64 wv = wdu[c * 9 + ky * 3 + kx];
                aA = fma2(pr[ky][kx], wv, aA);
                aB = fma2(pr[ky + 1][kx], wv, aB);
            }
        float2 A = up2(aA), Bv = up2(aB);
        float m = fmaxf(fmaxf(fmaxf(A.x, A.y), fmaxf(Bv.x, Bv.y)), 0.f);
        d_h1[b * 2048 + c * 256 + t] = m;
    }
}

// ---------------- conv2 (8->16, 16x16) + relu + maxpool2 -> 16x8x8 ----------------
// thread = (oc 0..15, oy 0..15); each computes one full 16-wide pre-pool row.
__global__ void __launch_bounds__(256) k_conv2(const float* __restrict__ w,
                                               const float* __restrict__ bias) {
    __shared__ float img[2048];      // 8 x 16 x 16
    __shared__ float2 wd[1152];      // 16 x 8 x 9, duplicated
    __shared__ float bs[16];
    int b = blockIdx.x, t = threadIdx.x;
    ((float4*)img)[t] = ((const float4*)d_h1)[b * 512 + t];
    ((float4*)img)[t + 256] = ((const float4*)d_h1)[b * 512 + t + 256];
    for (int i = t; i < 1152; i += 256) { float v = w[i]; wd[i] = make_float2(v, v); }
    if (t < 16) bs[t] = bias[t];
    __syncthreads();

    int oc = t >> 4, oy = t & 15;
    const float4* img4 = (const float4*)img;
    const u64* wdu = (const u64*)wd;
    u64 acc[8];
#pragma unroll
    for (int m = 0; m < 8; m++) acc[m] = pk1(bs[oc]);

    for (int ic = 0; ic < 8; ic++) {
#pragma unroll
        for (int ky = 0; ky < 3; ky++) {
            int iy = oy - 1 + ky;
            float4 ra, rb, rc, rd;
            if ((unsigned)iy < 16u) {
                int o = ic * 64 + iy * 4;
                ra = img4[o]; rb = img4[o + 1]; rc = img4[o + 2]; rd = img4[o + 3];
            } else {
                ra = rb = rc = rd = make_float4(0.f, 0.f, 0.f, 0.f);
            }
            u64 pr[17];
            pr[0] = pk(0.f, ra.x);
            pr[1] = pk(ra.x, ra.y);  pr[2] = pk(ra.y, ra.z);  pr[3] = pk(ra.z, ra.w);
            pr[4] = pk(ra.w, rb.x);
            pr[5] = pk(rb.x, rb.y);  pr[6] = pk(rb.y, rb.z);  pr[7] = pk(rb.z, rb.w);
            pr[8] = pk(rb.w, rc.x);
            pr[9] = pk(rc.x, rc.y);  pr[10] = pk(rc.y, rc.z); pr[11] = pk(rc.z, rc.w);
            pr[12] = pk(rc.w, rd.x);
            pr[13] = pk(rd.x, rd.y); pr[14] = pk(rd.y, rd.z); pr[15] = pk(rd.z, rd.w);
            pr[16] = pk(rd.w, 0.f);
#pragma unroll
            for (int kx = 0; kx < 3; kx++) {
                u64 wv = wdu[oc * 72 + ic * 9 + ky * 3 + kx];
#pragma unroll
                for (int m = 0; m < 8; m++) acc[m] = fma2(pr[2 * m + kx], wv, acc[m]);
            }
        }
    }
    // horizontal 2-max, then vertical via neighbor lane (oy pairs), relu
    float h[8];
#pragma unroll
    for (int m = 0; m < 8; m++) { float2 v = up2(acc[m]); h[m] = fmaxf(v.x, v.y); }
#pragma unroll
    for (int m = 0; m < 8; m++) {
        float o = __shfl_xor_sync(0xffffffffu, h[m], 1);
        h[m] = fmaxf(fmaxf(h[m], o), 0.f);
    }
    if ((oy & 1) == 0) {
        float4* dst = (float4*)&d_h2[b * 1024 + oc * 64 + (oy >> 1) * 8];
        dst[0] = make_float4(h[0], h[1], h[2], h[3]);
        dst[1] = make_float4(h[4], h[5], h[6], h[7]);
    }
}

// ---------------- conv3 (16->32, 8x8) + relu + spatial mean -> feats (32) ----------------
__global__ void __launch_bounds__(256) k_conv3(const float* __restrict__ w,
                                               const float* __restrict__ bias) {
    __shared__ float img[1024];      // 16 x 8 x 8
    __shared__ float2 wd[4608];      // 32 x 16 x 9, duplicated
    __shared__ float bs[32];
    int b = blockIdx.x, t = threadIdx.x;
    ((float4*)img)[t] = ((const float4*)d_h2)[b * 256 + t];
    for (int i = t; i < 4608; i += 256) { float v = w[i]; wd[i] = make_float2(v, v); }
    if (t < 32) bs[t] = bias[t];
    __syncthreads();

    int oc = t >> 3, oy = t & 7;
    const float4* img4 = (const float4*)img;
    const u64* wdu = (const u64*)wd;
    u64 acc[4];
#pragma unroll
    for (int m = 0; m < 4; m++) acc[m] = pk1(bs[oc]);

    for (int ic = 0; ic < 16; ic++) {
#pragma unroll
        for (int ky = 0; ky < 3; ky++) {
            int iy = oy - 1 + ky;
            float4 ra, rb;
            if ((unsigned)iy < 8u) {
                int o = ic * 16 + iy * 2;
                ra = img4[o]; rb = img4[o + 1];
            } else {
                ra = rb = make_float4(0.f, 0.f, 0.f, 0.f);
            }
            u64 pr[9];
            pr[0] = pk(0.f, ra.x);
            pr[1] = pk(ra.x, ra.y); pr[2] = pk(ra.y, ra.z); pr[3] = pk(ra.z, ra.w);
            pr[4] = pk(ra.w, rb.x);
            pr[5] = pk(rb.x, rb.y); pr[6] = pk(rb.y, rb.z); pr[7] = pk(rb.z, rb.w);
            pr[8] = pk(rb.w, 0.f);
#pragma unroll
            for (int kx = 0; kx < 3; kx++) {
                u64 wv = wdu[oc * 144 + ic * 9 + ky * 3 + kx];
#pragma unroll
                for (int m = 0; m < 4; m++) acc[m] = fma2(pr[2 * m + kx], wv, acc[m]);
            }
        }
    }
    float partial = 0.f;
#pragma unroll
    for (int m = 0; m < 4; m++) {
        float2 v = up2(acc[m]);
        partial += fmaxf(v.x, 0.f) + fmaxf(v.y, 0.f);
    }
    int sub = t & 7;
#pragma unroll
    for (int off = 4; off; off >>= 1) {
        float o = __shfl_down_sync(0xffffffffu, partial, off, 8);
        if (sub + off < 8) partial += o;
    }
    if (sub == 0) d_feats[b * 32 + oc] = partial * (1.f / 64.f);
}

// ---------------- GNN: a=tanh(f W1^T), g=tanh(a W2^T), q/k via 4x4 rotation ----------------
__global__ void __launch_bounds__(256) k_gnn(const float* __restrict__ w1,
                                             const float* __restrict__ w2,
                                             const float* __restrict__ R, int B) {
    __shared__ float w1s[32 * 33];
    __shared__ float w2s[16 * 33];
    __shared__ float Rs[16];
    __shared__ float fs[8][32];
    __shared__ float as_[8][32];
    __shared__ float gs[8][16];
    int t = threadIdx.x, wrp = t >> 5, lane = t & 31;
    for (int i = t; i < 1024; i += 256) w1s[(i >> 5) * 33 + (i & 31)] = w1[i];
    for (int i = t; i < 512; i += 256) w2s[(i >> 5) * 33 + (i & 31)] = w2[i];
    if (t < 16) Rs[t] = R[t];
    __syncthreads();

    int row = blockIdx.x * 8 + wrp;
    if (row >= B) return;
    fs[wrp][lane] = d_feats[row * 32 + lane];
    __syncwarp();
    float a = 0.f;
#pragma unroll
    for (int i = 0; i < 32; i++) a += fs[wrp][i] * w1s[lane * 33 + i];
    as_[wrp][lane] = tanhf(a);
    __syncwarp();
    if (lane < 16) {
        float gg = 0.f;
#pragma unroll
        for (int i = 0; i < 32; i++) gg += as_[wrp][i] * w2s[lane * 33 + i];
        gg = tanhf(gg);
        gs[wrp][lane] = gg;
        d_g[row * 16 + lane] = gg;
    }
    __syncwarp();
    if (lane < 16) {
        int r = lane >> 2, cc = lane & 3;
        float qv = 0.f, kv = 0.f;
#pragma unroll
        for (int m = 0; m < 4; m++) {
            float gm = gs[wrp][r * 4 + m];
            qv += gm * Rs[m * 4 + cc];
            kv += gm * Rs[cc * 4 + m];
        }
        d_q[row * 16 + lane] = qv;
        d_k[row * 16 + lane] = kv;
    }
}

// ---------------- attention: one-pass softmax with analytic max bound ----------------
// 32 rows/block, 16 threads/row (512 threads); k/g tiles of 256 rows in smem.
__global__ void __launch_bounds__(512) k_attn(const float* __restrict__ R,
                                              const float* __restrict__ ent, int B) {
    __shared__ float4 kt4[1024];
    __shared__ float4 gt4[1024];
    int t = threadIdx.x;
    int r = t >> 4, part = t & 15;
    int row0 = blockIdx.x * 32 + r;
    int row = min(row0, B - 1);

    float temp = (cosf(ent[0]) + cosf(ent[1]) + cosf(ent[2])) * (1.f / 3.f);
    float scale = temp * 0.25f;
    // bound: |k_j|^2 <= 4 * sum_c (sum_m |R[c,m]|)^2  (|g| elementwise < 1)
    float sum2 = 0.f;
#pragma unroll
    for (int c = 0; c < 4; c++) {
        float rs = fabsf(R[c * 4]) + fabsf(R[c * 4 + 1]) + fabsf(R[c * 4 + 2]) + fabsf(R[c * 4 + 3]);
        sum2 += rs * rs;
    }
    float kb = 2.f * sqrtf(sum2);

    const float4* q4 = (const float4*)d_q + row * 4;
    float4 q0 = q4[0], q1 = q4[1], q2 = q4[2], q3 = q4[3];
    u64 qp[8] = { pk(q0.x, q0.y), pk(q0.z, q0.w), pk(q1.x, q1.y), pk(q1.z, q1.w),
                  pk(q2.x, q2.y), pk(q2.z, q2.w), pk(q3.x, q3.y), pk(q3.z, q3.w) };
    float qn2 = q0.x * q0.x + q0.y * q0.y + q0.z * q0.z + q0.w * q0.w
              + q1.x * q1.x + q1.y * q1.y + q1.z * q1.z + q1.w * q1.w
              + q2.x * q2.x + q2.y * q2.y + q2.z * q2.z + q2.w * q2.w
              + q3.x * q3.x + q3.y * q3.y + q3.z * q3.z + q3.w * q3.w;
    float M = sqrtf(qn2) * kb * fabsf(scale);   // >= max_j |logit|

    u64 acc[8];
#pragma unroll
    for (int d = 0; d < 8; d++) acc[d] = pk1(0.f);
    float s = 0.f;

    int ntiles = (B + 255) >> 8;
    for (int jt = 0; jt < ntiles; jt++) {
        int base = jt << 8;
        int cnt = min(256, B - base);
        __syncthreads();
        for (int i = t; i < cnt * 4; i += 512) {
            kt4[i] = ((const float4*)d_k)[base * 4 + i];
            gt4[i] = ((const float4*)d_g)[base * 4 + i];
        }
        __syncthreads();
        for (int jj = part; jj < cnt; jj += 16) {
            float4 k0 = kt4[jj * 4], k1 = kt4[jj * 4 + 1], k2 = kt4[jj * 4 + 2], k3 = kt4[jj * 4 + 3];
            u64 d2 = mul2(qp[0], pk(k0.x, k0.y));
            d2 = fma2(qp[1], pk(k0.z, k0.w), d2);
            d2 = fma2(qp[2], pk(k1.x, k1.y), d2);
            d2 = fma2(qp[3], pk(k1.z, k1.w), d2);
            d2 = fma2(qp[4], pk(k2.x, k2.y), d2);
            d2 = fma2(qp[5], pk(k2.z, k2.w), d2);
            d2 = fma2(qp[6], pk(k3.x, k3.y), d2);
            d2 = fma2(qp[7], pk(k3.z, k3.w), d2);
            float2 dd = up2(d2);
            float pe = __expf((dd.x + dd.y) * scale - M);
            s += pe;
            u64 pe2 = pk1(pe);
            float4 g0 = gt4[jj * 4], g1 = gt4[jj * 4 + 1], g2 = gt4[jj * 4 + 2], g3 = gt4[jj * 4 + 3];
            acc[0] = fma2(pe2, pk(g0.x, g0.y), acc[0]);
            acc[1] = fma2(pe2, pk(g0.z, g0.w), acc[1]);
            acc[2] = fma2(pe2, pk(g1.x, g1.y), acc[2]);
            acc[3] = fma2(pe2, pk(g1.z, g1.w), acc[3]);
            acc[4] = fma2(pe2, pk(g2.x, g2.y), acc[4]);
            acc[5] = fma2(pe2, pk(g2.z, g2.w), acc[5]);
            acc[6] = fma2(pe2, pk(g3.x, g3.y), acc[6]);
            acc[7] = fma2(pe2, pk(g3.z, g3.w), acc[7]);
        }
    }
    // butterfly reduce across the 16 parts of this row (lane bits 0..3)
#pragma unroll
    for (int off = 1; off < 16; off <<= 1) {
        s += __shfl_xor_sync(0xffffffffu, s, off);
#pragma unroll
        for (int d = 0; d < 8; d++)
            acc[d] = add2(acc[d], __shfl_xor_sync(0xffffffffu, acc[d], off));
    }
    if (part == 0 && row0 < B) {
        float inv = 1.f / s;
        float4* dst = (float4*)d_attn + row * 4;
#pragma unroll
        for (int kq = 0; kq < 4; kq++) {
            float2 a = up2(acc[2 * kq]), bq = up2(acc[2 * kq + 1]);
            dst[kq] = make_float4(a.x * inv, a.y * inv, bq.x * inv, bq.y * inv);
        }
    }
}

// ---------------- head: [g,attn] @ reduce_w^T + rb -> @ cls_w^T + cb ----------------
__global__ void __launch_bounds__(256) k_head(const float* __restrict__ rw,
                                              const float* __restrict__ rb,
                                              const float* __restrict__ cw,
                                              const float* __restrict__ cb, int B) {
    int i = blockIdx.x * 256 + threadIdx.x;
    if (i >= B) return;
    float r0 = rb[0], r1 = rb[1];
#pragma unroll
    for (int d = 0; d < 16; d++) {
        float gv = d_g[i * 16 + d];
        float av = d_attn[i * 16 + d];
        r0 += gv * rw[d] + av * rw[16 + d];
        r1 += gv * rw[32 + d] + av * rw[48 + d];
    }
    d_outpre[i * 2 + 0] = cb[0] + r0 * cw[0] + r1 * cw[1];
    d_outpre[i * 2 + 1] = cb[1] + r0 * cw[2] + r1 * cw[3];
}

// ---------------- batch-norm stats (1 block, deterministic) ----------------
__global__ void __launch_bounds__(256) k_stats(const float* __restrict__ gamma,
                                               const float* __restrict__ beta, int B) {
    __shared__ float sh[1024];
    int t = threadIdx.x;
    float s0 = 0.f, s1 = 0.f, q0 = 0.f, q1 = 0.f;
    for (int i = t; i < B; i += 256) {
        float a = d_outpre[i * 2], b2 = d_outpre[i * 2 + 1];
        s0 += a; q0 += a * a; s1 += b2; q1 += b2 * b2;
    }
    sh[t] = s0; sh[256 + t] = s1; sh[512 + t] = q0; sh[768 + t] = q1;
    __syncthreads();
    for (int off = 128; off; off >>= 1) {
        if (t < off) {
            sh[t] += sh[t + off];
            sh[256 + t] += sh[256 + t + off];
            sh[512 + t] += sh[512 + t + off];
            sh[768 + t] += sh[768 + t + off];
        }
        __syncthreads();
    }
    if (t == 0) {
        float invB = 1.f / (float)B;
        float mu0 = sh[0] * invB, mu1 = sh[256] * invB;
        float v0 = sh[512] * invB - mu0 * mu0;
        float v1 = sh[768] * invB - mu1 * mu1;
        float A0 = gamma[0] * rsqrtf(v0 + 1e-5f);
        float A1 = gamma[1] * rsqrtf(v1 + 1e-5f);
        d_ab[0] = A0; d_ab[1] = A1;
        d_ab[2] = beta[0] - mu0 * A0;
        d_ab[3] = beta[1] - mu1 * A1;
    }
}

__global__ void __launch_bounds__(256) k_norm(float* __restrict__ out, int B) {
    int i = blockIdx.x * 256 + threadIdx.x;
    if (i >= B) return;
    out[i * 2 + 0] = d_outpre[i * 2 + 0] * d_ab[0] + d_ab[2];
    out[i * 2 + 1] = d_outpre[i * 2 + 1] * d_ab[1] + d_ab[3];
}

// ---------------- launch ----------------
extern "C" void kernel_launch(void* const* d_in, const int* in_sizes, int n_in,
                              void* d_out, int out_size) {
    const float* x   = (const float*)d_in[0];
    const float* c1w = (const float*)d_in[1];
    const float* c1b = (const float*)d_in[2];
    const float* c2w = (const float*)d_in[3];
    const float* c2b = (const float*)d_in[4];
    const float* c3w = (const float*)d_in[5];
    const float* c3b = (const float*)d_in[6];
    const float* g1  = (const float*)d_in[7];
    const float* g2  = (const float*)d_in[8];
    const float* rot = (const float*)d_in[9];
    const float* ent = (const float*)d_in[10];
    const float* rw  = (const float*)d_in[11];
    const float* rb  = (const float*)d_in[12];
    const float* cw  = (const float*)d_in[13];
    const float* cb  = (const float*)d_in[14];
    const float* gam = (const float*)d_in[15];
    const float* bet = (const float*)d_in[16];

    int B = in_sizes[0] / 1024;

    k_conv1<<<B, 256>>>(x, c1w, c1b);
    k_conv2<<<B, 256>>>(c2w, c2b);
    k_conv3<<<B, 256>>>(c3w, c3b);
    k_gnn<<<(B + 7) / 8, 256>>>(g1, g2, rot, B);
    k_attn<<<(B + 31) / 32, 512>>>(rot, ent, B);
    k_head<<<(B + 255) / 256, 256>>>(rw, rb, cw, cb, B);
    k_stats<<<1, 256>>>(gam, bet, B);
    k_norm<<<(B + 255) / 256, 256>>>((float*)d_out, B);
}

// round 3
// speedup vs baseline: 1.4052x; 1.4052x over previous
#include <cuda_runtime.h>
#include <math.h>

// ---------------- scratch (static device globals; no allocation) ----------------
#define BMAX 4096
__device__ __align__(16) float d_g[BMAX * 16];
__device__ __align__(16) float d_q[BMAX * 16];
__device__ __align__(16) float d_k[BMAX * 16];
__device__ __align__(16) float d_outpre[BMAX * 2];
__device__ float d_ab[4];

// ---------------- fused conv1+pool+conv2+pool+conv3+mean+gnn ----------------
// dynamic smem layout (float offsets)
#define O_WC1   0       // 72
#define O_BS1   72      // 8
#define O_WC2   80      // 1152
#define O_BS2   1232    // 16
#define O_WC3   1248    // 4608
#define O_BS3   5856    // 32
#define O_W1    5888    // 32*33 = 1056
#define O_W2    6944    // 16*33 = 528
#define O_R     7472    // 16
#define O_IMG   7488    // 34*36 = 1224
#define O_H1    8712    // 8*18*20 = 2880
#define O_H2    11592   // 16*10*12 = 1920
#define O_FEAT  13512   // 32
#define O_AVEC  13544   // 32
#define O_GVEC  13576   // 16
#define SM_FLOATS 13592
#define SM_BYTES  (SM_FLOATS * 4)

__global__ void __launch_bounds__(256) k_feat(
    const float* __restrict__ x,
    const float* __restrict__ c1w, const float* __restrict__ c1b,
    const float* __restrict__ c2w, const float* __restrict__ c2b,
    const float* __restrict__ c3w, const float* __restrict__ c3b,
    const float* __restrict__ w1, const float* __restrict__ w2,
    const float* __restrict__ R)
{
    extern __shared__ __align__(16) float sm[];
    float* wc1 = sm + O_WC1;  float* bs1 = sm + O_BS1;
    float* wc2 = sm + O_WC2;  float* bs2 = sm + O_BS2;
    float* wc3 = sm + O_WC3;  float* bs3 = sm + O_BS3;
    float* w1s = sm + O_W1;   float* w2s = sm + O_W2;
    float* Rs  = sm + O_R;
    float* img = sm + O_IMG;  float* h1 = sm + O_H1;  float* h2 = sm + O_H2;
    float* feats = sm + O_FEAT; float* avec = sm + O_AVEC; float* gvec = sm + O_GVEC;

    int b = blockIdx.x, t = threadIdx.x;

    // zero padded activation buffers (halos must be 0)
    {
        float4 z = make_float4(0.f, 0.f, 0.f, 0.f);
        float4* p1 = (float4*)img;  // 306
        float4* p2 = (float4*)h1;   // 720
        float4* p3 = (float4*)h2;   // 480
        for (int i = t; i < 306; i += 256) p1[i] = z;
        for (int i = t; i < 720; i += 256) p2[i] = z;
        for (int i = t; i < 480; i += 256) p3[i] = z;
    }
    // load weights
    for (int i = t; i < 72; i += 256) wc1[i] = c1w[i];
    if (t < 8)  bs1[t] = c1b[t];
    for (int i = t; i < 288; i += 256)  ((float4*)wc2)[i] = ((const float4*)c2w)[i];
    if (t < 16) bs2[t] = c2b[t];
    for (int i = t; i < 1152; i += 256) ((float4*)wc3)[i] = ((const float4*)c3w)[i];
    if (t < 32) bs3[t] = c3b[t];
    for (int i = t; i < 1024; i += 256) w1s[(i >> 5) * 33 + (i & 31)] = w1[i];
    for (int i = t; i < 512; i += 256)  w2s[(i >> 5) * 33 + (i & 31)] = w2[i];
    if (t < 16) Rs[t] = R[t];
    __syncthreads();

    // load input image into padded interior (34 x 36, interior rows/cols 1..32)
    {
        float4 v = ((const float4*)x)[b * 256 + t];
        int r = t >> 3, c = (t & 7) * 4;
        float* dst = img + (r + 1) * 36 + c + 1;
        dst[0] = v.x; dst[1] = v.y; dst[2] = v.z; dst[3] = v.w;
    }
    __syncthreads();

    // ---- stage 1: conv1 (1->8) + relu + pool -> h1 padded interior ----
    {
        int ph = t >> 4, pw = t & 15;
        float p[4][4];
#pragma unroll
        for (int yy = 0; yy < 4; yy++)
#pragma unroll
            for (int xx = 0; xx < 4; xx++)
                p[yy][xx] = img[(2 * ph + yy) * 36 + 2 * pw + xx];
#pragma unroll
        for (int c = 0; c < 8; c++) {
            float a00 = bs1[c], a01 = a00, a10 = a00, a11 = a00;
#pragma unroll
            for (int ky = 0; ky < 3; ky++)
#pragma unroll
                for (int kx = 0; kx < 3; kx++) {
                    float w = wc1[c * 9 + ky * 3 + kx];
                    a00 += p[ky][kx] * w;     a01 += p[ky][kx + 1] * w;
                    a10 += p[ky + 1][kx] * w; a11 += p[ky + 1][kx + 1] * w;
                }
            float m = fmaxf(fmaxf(fmaxf(a00, a01), fmaxf(a10, a11)), 0.f);
            h1[c * 360 + (ph + 1) * 20 + (pw + 1)] = m;
        }
    }
    __syncthreads();

    // ---- stage 2: conv2 (8->16) + relu + pool -> h2 padded interior ----
    {
        int c0 = t >> 6, pos = t & 63, ph = pos >> 3, pw = pos & 7;
        float acc[4][4];
#pragma unroll
        for (int oo = 0; oo < 4; oo++) {
            float bv = bs2[c0 + 4 * oo];
            acc[oo][0] = bv; acc[oo][1] = bv; acc[oo][2] = bv; acc[oo][3] = bv;
        }
#pragma unroll 1
        for (int ic = 0; ic < 8; ic++) {
            float p[4][4];
            const float* hp = h1 + ic * 360 + 2 * ph * 20 + 2 * pw;
#pragma unroll
            for (int yy = 0; yy < 4; yy++)
#pragma unroll
                for (int xx = 0; xx < 4; xx++)
                    p[yy][xx] = hp[yy * 20 + xx];
#pragma unroll
            for (int oo = 0; oo < 4; oo++) {
                const float* wp = wc2 + (c0 + 4 * oo) * 72 + ic * 9;
#pragma unroll
                for (int ky = 0; ky < 3; ky++)
#pragma unroll
                    for (int kx = 0; kx < 3; kx++) {
                        float w = wp[ky * 3 + kx];
                        acc[oo][0] += p[ky][kx] * w;     acc[oo][1] += p[ky][kx + 1] * w;
                        acc[oo][2] += p[ky + 1][kx] * w; acc[oo][3] += p[ky + 1][kx + 1] * w;
                    }
            }
        }
#pragma unroll
        for (int oo = 0; oo < 4; oo++) {
            float m = fmaxf(fmaxf(acc[oo][0], acc[oo][1]), fmaxf(acc[oo][2], acc[oo][3]));
            m = fmaxf(m, 0.f);
            h2[(c0 + 4 * oo) * 120 + (ph + 1) * 12 + (pw + 1)] = m;
        }
    }
    __syncthreads();

    // ---- stage 3: conv3 (16->32) + relu + spatial mean -> feats[32] ----
    {
        int oc = t >> 3, oy = t & 7;
        float acc[8];
#pragma unroll
        for (int ox = 0; ox < 8; ox++) acc[ox] = bs3[oc];
#pragma unroll 1
        for (int ic = 0; ic < 16; ic++) {
            const float4* rp = (const float4*)(h2 + ic * 120 + oy * 12);
            const float* wp = wc3 + oc * 144 + ic * 9;
#pragma unroll
            for (int ky = 0; ky < 3; ky++) {
                float4 ra = rp[ky * 3], rb = rp[ky * 3 + 1], rc = rp[ky * 3 + 2];
                float row[10] = { ra.x, ra.y, ra.z, ra.w, rb.x, rb.y, rb.z, rb.w, rc.x, rc.y };
#pragma unroll
                for (int kx = 0; kx < 3; kx++) {
                    float w = wp[ky * 3 + kx];
#pragma unroll
                    for (int ox = 0; ox < 8; ox++) acc[ox] += row[ox + kx] * w;
                }
            }
        }
        float s = 0.f;
#pragma unroll
        for (int ox = 0; ox < 8; ox++) s += fmaxf(acc[ox], 0.f);
        int sub = t & 7;
#pragma unroll
        for (int off = 4; off; off >>= 1) {
            float o = __shfl_down_sync(0xffffffffu, s, off, 8);
            if (sub + off < 8) s += o;
        }
        if (sub == 0) feats[oc] = s * (1.f / 64.f);
    }
    __syncthreads();

    // ---- gnn on warp 0: a=tanh(W1 f), g=tanh(W2 a), q/k via R ----
    if (t < 32) {
        float a = 0.f;
#pragma unroll
        for (int i = 0; i < 32; i++) a += feats[i] * w1s[t * 33 + i];
        avec[t] = tanhf(a);
        __syncwarp();
        if (t < 16) {
            float g = 0.f;
#pragma unroll
            for (int i = 0; i < 32; i++) g += avec[i] * w2s[t * 33 + i];
            g = tanhf(g);
            gvec[t] = g;
            d_g[b * 16 + t] = g;
        }
        __syncwarp();
        if (t < 16) {
            int r = t >> 2, cc = t & 3;
            float qv = 0.f, kv = 0.f;
#pragma unroll
            for (int m = 0; m < 4; m++) {
                float gm = gvec[r * 4 + m];
                qv += gm * Rs[m * 4 + cc];
                kv += gm * Rs[cc * 4 + m];
            }
            d_q[b * 16 + t] = qv;
            d_k[b * 16 + t] = kv;
        }
    }
}

// ---------------- attention (one-pass, analytic max bound) + head ----------------
// 16 rows/block, 16 parts/row (256 threads); k/g tiles of 256 rows in smem.
__global__ void __launch_bounds__(256) k_attn(
    const float* __restrict__ R, const float* __restrict__ ent,
    const float* __restrict__ rw, const float* __restrict__ rb,
    const float* __restrict__ cw, const float* __restrict__ cb, int B)
{
    __shared__ __align__(16) float4 kt4[256 * 4];
    __shared__ __align__(16) float4 gt4[256 * 4];
    int t = threadIdx.x;
    int r = t >> 4, part = t & 15;
    int row0 = blockIdx.x * 16 + r;
    int row = min(row0, B - 1);

    float temp = (cosf(ent[0]) + cosf(ent[1]) + cosf(ent[2])) * (1.f / 3.f);
    float scale = temp * 0.25f;
    // |logit| <= |q| * 2*sqrt(sum_c (sum_m |R[c,m]|)^2) * |scale|   (|g|<1 elementwise)
    float sum2 = 0.f;
#pragma unroll
    for (int c = 0; c < 4; c++) {
        float rs = fabsf(R[c * 4]) + fabsf(R[c * 4 + 1]) + fabsf(R[c * 4 + 2]) + fabsf(R[c * 4 + 3]);
        sum2 += rs * rs;
    }
    float kb = 2.f * sqrtf(sum2);

    const float4* q4 = (const float4*)d_q + row * 4;
    float4 q0 = q4[0], q1 = q4[1], q2 = q4[2], q3 = q4[3];
    float qn2 = q0.x * q0.x + q0.y * q0.y + q0.z * q0.z + q0.w * q0.w
              + q1.x * q1.x + q1.y * q1.y + q1.z * q1.z + q1.w * q1.w
              + q2.x * q2.x + q2.y * q2.y + q2.z * q2.z + q2.w * q2.w
              + q3.x * q3.x + q3.y * q3.y + q3.z * q3.z + q3.w * q3.w;
    float M = sqrtf(qn2) * kb * fabsf(scale);   // >= max_j |logit|

    float acc[16];
#pragma unroll
    for (int d = 0; d < 16; d++) acc[d] = 0.f;
    float s = 0.f;

    int ntiles = (B + 255) >> 8;
    for (int jt = 0; jt < ntiles; jt++) {
        int base = jt << 8;
        int cnt = min(256, B - base);
        __syncthreads();
        for (int i = t; i < cnt * 4; i += 256) {
            kt4[i] = ((const float4*)d_k)[base * 4 + i];
            gt4[i] = ((const float4*)d_g)[base * 4 + i];
        }
        __syncthreads();
        for (int jj = part; jj < cnt; jj += 16) {
            float4 k0 = kt4[jj * 4], k1 = kt4[jj * 4 + 1], k2 = kt4[jj * 4 + 2], k3 = kt4[jj * 4 + 3];
            float dot = q0.x * k0.x + q0.y * k0.y + q0.z * k0.z + q0.w * k0.w
                      + q1.x * k1.x + q1.y * k1.y + q1.z * k1.z + q1.w * k1.w
                      + q2.x * k2.x + q2.y * k2.y + q2.z * k2.z + q2.w * k2.w
                      + q3.x * k3.x + q3.y * k3.y + q3.z * k3.z + q3.w * k3.w;
            float pe = __expf(dot * scale - M);
            s += pe;
            float4 g0 = gt4[jj * 4], g1 = gt4[jj * 4 + 1], g2 = gt4[jj * 4 + 2], g3 = gt4[jj * 4 + 3];
            acc[0]  += pe * g0.x; acc[1]  += pe * g0.y; acc[2]  += pe * g0.z; acc[3]  += pe * g0.w;
            acc[4]  += pe * g1.x; acc[5]  += pe * g1.y; acc[6]  += pe * g1.z; acc[7]  += pe * g1.w;
            acc[8]  += pe * g2.x; acc[9]  += pe * g2.y; acc[10] += pe * g2.z; acc[11] += pe * g2.w;
            acc[12] += pe * g3.x; acc[13] += pe * g3.y; acc[14] += pe * g3.z; acc[15] += pe * g3.w;
        }
    }
    // butterfly reduce across 16 parts (lane bits 0..3)
#pragma unroll
    for (int off = 1; off < 16; off <<= 1) {
        s += __shfl_xor_sync(0xffffffffu, s, off);
#pragma unroll
        for (int d = 0; d < 16; d++)
            acc[d] += __shfl_xor_sync(0xffffffffu, acc[d], off);
    }
    if (part == 0 && row0 < B) {
        float inv = 1.f / s;
        // fused head: r0/r1 = [g, attn] @ reduce_w^T + rb ; out = @ cls_w^T + cb
        float r0 = rb[0], r1 = rb[1];
        const float* gp = d_g + row * 16;
#pragma unroll
        for (int d = 0; d < 16; d++) {
            float gv = gp[d];
            float av = acc[d] * inv;
            r0 += gv * rw[d] + av * rw[16 + d];
            r1 += gv * rw[32 + d] + av * rw[48 + d];
        }
        d_outpre[row * 2 + 0] = cb[0] + r0 * cw[0] + r1 * cw[1];
        d_outpre[row * 2 + 1] = cb[1] + r0 * cw[2] + r1 * cw[3];
    }
}

// ---------------- batch-norm stats (1 block, deterministic) ----------------
__global__ void __launch_bounds__(256) k_stats(const float* __restrict__ gamma,
                                               const float* __restrict__ beta, int B) {
    __shared__ float sh[1024];
    int t = threadIdx.x;
    float s0 = 0.f, s1 = 0.f, q0 = 0.f, q1 = 0.f;
    for (int i = t; i < B; i += 256) {
        float a = d_outpre[i * 2], b2 = d_outpre[i * 2 + 1];
        s0 += a; q0 += a * a; s1 += b2; q1 += b2 * b2;
    }
    sh[t] = s0; sh[256 + t] = s1; sh[512 + t] = q0; sh[768 + t] = q1;
    __syncthreads();
    for (int off = 128; off; off >>= 1) {
        if (t < off) {
            sh[t] += sh[t + off];
            sh[256 + t] += sh[256 + t + off];
            sh[512 + t] += sh[512 + t + off];
            sh[768 + t] += sh[768 + t + off];
        }
        __syncthreads();
    }
    if (t == 0) {
        float invB = 1.f / (float)B;
        float mu0 = sh[0] * invB, mu1 = sh[256] * invB;
        float v0 = sh[512] * invB - mu0 * mu0;
        float v1 = sh[768] * invB - mu1 * mu1;
        float A0 = gamma[0] * rsqrtf(v0 + 1e-5f);
        float A1 = gamma[1] * rsqrtf(v1 + 1e-5f);
        d_ab[0] = A0; d_ab[1] = A1;
        d_ab[2] = beta[0] - mu0 * A0;
        d_ab[3] = beta[1] - mu1 * A1;
    }
}

__global__ void __launch_bounds__(256) k_norm(float* __restrict__ out, int B) {
    int i = blockIdx.x * 256 + threadIdx.x;
    if (i >= B) return;
    out[i * 2 + 0] = d_outpre[i * 2 + 0] * d_ab[0] + d_ab[2];
    out[i * 2 + 1] = d_outpre[i * 2 + 1] * d_ab[1] + d_ab[3];
}

// ---------------- launch ----------------
extern "C" void kernel_launch(void* const* d_in, const int* in_sizes, int n_in,
                              void* d_out, int out_size) {
    const float* x   = (const float*)d_in[0];
    const float* c1w = (const float*)d_in[1];
    const float* c1b = (const float*)d_in[2];
    const float* c2w = (const float*)d_in[3];
    const float* c2b = (const float*)d_in[4];
    const float* c3w = (const float*)d_in[5];
    const float* c3b = (const float*)d_in[6];
    const float* g1  = (const float*)d_in[7];
    const float* g2  = (const float*)d_in[8];
    const float* rot = (const float*)d_in[9];
    const float* ent = (const float*)d_in[10];
    const float* rw  = (const float*)d_in[11];
    const float* rb  = (const float*)d_in[12];
    const float* cw  = (const float*)d_in[13];
    const float* cb  = (const float*)d_in[14];
    const float* gam = (const float*)d_in[15];
    const float* bet = (const float*)d_in[16];

    int B = in_sizes[0] / 1024;

    cudaFuncSetAttribute(k_feat, cudaFuncAttributeMaxDynamicSharedMemorySize, SM_BYTES);

    k_feat<<<B, 256, SM_BYTES>>>(x, c1w, c1b, c2w, c2b, c3w, c3b, g1, g2, rot);
    k_attn<<<(B + 15) / 16, 256>>>(rot, ent, rw, rb, cw, cb, B);
    k_stats<<<1, 256>>>(gam, bet, B);
    k_norm<<<(B + 255) / 256, 256>>>((float*)d_out, B);
}